// round 8
// baseline (speedup 1.0000x reference)
#include <cuda_runtime.h>
#include <cuda_bf16.h>
#include <cstdint>

// Problem constants
#define BATCH   64
#define NNODE   5000
#define CIN     64
#define COUT    64
#define DDIM    10
#define PLANE   (NNODE * CIN)       // 320000
#define NCOLS   (BATCH * CIN)       // 4096 GEMM output columns

// Padded GEMM dims
#define KPAD    5056                // 158 * 32
#define MPAD    5120                // 40 * 128

// GEMM tiling: 128x128 CTA tile, 4 warps of 64x64, 128 threads.
#define BM      128
#define BN      128
#define BKC     32
#define NKCH    (KPAD / BKC)        // 158
#define STAGES  2

#define APITCH  80                  // bytes per smem row (64B payload + 16B pad)
#define TILE_B  (128 * APITCH)      // 10240 B per tile
#define STAGE_B (4 * TILE_B)        // Ah, Al, Bh, Bl
#define GEMM_SMEM (STAGES * STAGE_B)  // 81920 B -> 2 CTAs/SM

// ---------------------------------------------------------------------------
// Device-global scratch (no allocations allowed)
// ---------------------------------------------------------------------------
__device__ __align__(256) __nv_bfloat16 g_Ahi[(size_t)MPAD * KPAD];
__device__ __align__(256) __nv_bfloat16 g_Alo[(size_t)MPAD * KPAD];
__device__ __align__(256) __nv_bfloat16 g_Bhi[(size_t)NCOLS * KPAD];
__device__ __align__(256) __nv_bfloat16 g_Blo[(size_t)NCOLS * KPAD];
__device__ __align__(256) float         g_y[(size_t)BATCH * PLANE];
// per-node transposed weights W_T[n][o][ki], bf16 hi/lo split
__device__ __align__(256) __nv_bfloat16 g_Wh[(size_t)NNODE * 8192];
__device__ __align__(256) __nv_bfloat16 g_Wl[(size_t)NNODE * 8192];

// ---------------------------------------------------------------------------
__device__ __forceinline__ uint32_t smem_u32(const void* p) {
    uint32_t a;
    asm("{ .reg .u64 t; cvta.to.shared.u64 t, %1; cvt.u32.u64 %0, t; }"
        : "=r"(a) : "l"(p));
    return a;
}

#define LDSM4(r0, r1, r2, r3, addr) \
    asm volatile("ldmatrix.sync.aligned.m8n8.x4.shared.b16 {%0,%1,%2,%3}, [%4];" \
                 : "=r"(r0), "=r"(r1), "=r"(r2), "=r"(r3) : "r"(addr))

#define MMA16816(d, a, b0, b1) \
    asm volatile("mma.sync.aligned.m16n8k16.row.col.f32.bf16.bf16.f32 " \
                 "{%0,%1,%2,%3}, {%4,%5,%6,%7}, {%8,%9}, {%0,%1,%2,%3};" \
                 : "+f"((d)[0]), "+f"((d)[1]), "+f"((d)[2]), "+f"((d)[3]) \
                 : "r"((a)[0]), "r"((a)[1]), "r"((a)[2]), "r"((a)[3]), \
                   "r"(b0), "r"(b1))

#define CPASYNC16(saddr, gaddr) \
    asm volatile("cp.async.cg.shared.global [%0], [%1], 16;" \
                 :: "r"(saddr), "l"(gaddr))

__device__ __forceinline__ void bf16_split(float f, __nv_bfloat16& hi, __nv_bfloat16& lo) {
    hi = __float2bfloat16(f);
    lo = __float2bfloat16(f - __bfloat162float(hi));
}

// ---------------------------------------------------------------------------
// Kernel 1: softmax(relu(E E^T)) row -> bf16 hi/lo, padded rows into g_Ahi/lo.
// ---------------------------------------------------------------------------
__global__ __launch_bounds__(256)
void support_split_kernel(const float* __restrict__ E)
{
    const int n   = blockIdx.x;
    const int tid = threadIdx.x;
    __nv_bfloat16* rh = g_Ahi + (size_t)n * KPAD;
    __nv_bfloat16* rl = g_Alo + (size_t)n * KPAD;

    if (n >= NNODE) {
        const __nv_bfloat16 z = __float2bfloat16(0.0f);
        for (int m = tid; m < KPAD; m += 256) { rh[m] = z; rl[m] = z; }
        return;
    }

    __shared__ float e_n[16];
    __shared__ float sE[256 * DDIM];
    __shared__ float red[256];

    if (tid < DDIM) e_n[tid] = E[n * DDIM + tid];
    __syncthreads();

    float v[20];
    float mx = 0.0f;   // relu >= 0
    for (int j = 0; j < 20; ++j) {
        int m0  = j * 256;
        int cnt = NNODE - m0; if (cnt > 256) cnt = 256;
        __syncthreads();
        for (int idx = tid; idx < cnt * DDIM; idx += 256)
            sE[idx] = E[m0 * DDIM + idx];
        __syncthreads();
        int m = m0 + tid;
        if (m < NNODE) {
            float dot = 0.0f;
            #pragma unroll
            for (int d = 0; d < DDIM; ++d) dot += e_n[d] * sE[tid * DDIM + d];
            dot = fmaxf(dot, 0.0f);
            v[j] = dot;
            mx = fmaxf(mx, dot);
        } else v[j] = 0.0f;
    }

    red[tid] = mx; __syncthreads();
    for (int s = 128; s > 0; s >>= 1) {
        if (tid < s) red[tid] = fmaxf(red[tid], red[tid + s]);
        __syncthreads();
    }
    mx = red[0];
    __syncthreads();

    float sum = 0.0f;
    #pragma unroll
    for (int j = 0; j < 20; ++j) {
        int m = j * 256 + tid;
        if (m < NNODE) { v[j] = __expf(v[j] - mx); sum += v[j]; }
    }
    red[tid] = sum; __syncthreads();
    for (int s = 128; s > 0; s >>= 1) {
        if (tid < s) red[tid] += red[tid + s];
        __syncthreads();
    }
    const float inv = 1.0f / red[0];

    #pragma unroll
    for (int j = 0; j < 20; ++j) {
        int m = j * 256 + tid;
        if (m < NNODE) {
            __nv_bfloat16 hi, lo;
            bf16_split(v[j] * inv, hi, lo);
            rh[m] = hi; rl[m] = lo;
        } else if (m < KPAD) {
            rh[m] = __float2bfloat16(0.0f);
            rl[m] = __float2bfloat16(0.0f);
        }
    }
}

// ---------------------------------------------------------------------------
// Kernel 2: build B^T hi/lo: Bmat[col][k] = x[b,k,c], col = b*64+c, padded K.
// ---------------------------------------------------------------------------
__global__ __launch_bounds__(256)
void convert_b_kernel(const float* __restrict__ X)
{
    __shared__ float t[32][33];
    const int tx = threadIdx.x, ty = threadIdx.y;
    const int c0 = blockIdx.x * 32;
    const int k0 = blockIdx.y * 32;
    const int b  = c0 >> 6;
    const int cc = c0 & 63;

    #pragma unroll
    for (int i = 0; i < 4; ++i) {
        int row = k0 + ty + i * 8;
        t[ty + i * 8][tx] = (row < NNODE)
            ? X[(size_t)b * PLANE + (size_t)row * CIN + cc + tx] : 0.0f;
    }
    __syncthreads();

    #pragma unroll
    for (int i = 0; i < 4; ++i) {
        int colr = ty + i * 8;
        __nv_bfloat16 hi, lo;
        bf16_split(t[tx][colr], hi, lo);
        size_t off = (size_t)(c0 + colr) * KPAD + k0 + tx;
        g_Bhi[off] = hi;
        g_Blo[off] = lo;
    }
}

// ---------------------------------------------------------------------------
// Kernel 3: W_T build.  W_T[n][o][ki] = sum_d E[n,d] * wp[d][ki][o], bf16 split.
// ---------------------------------------------------------------------------
__global__ __launch_bounds__(256)
void wbuild_kernel(const float* __restrict__ E, const float* __restrict__ wp)
{
    __shared__ float e_sh[8][DDIM];
    const int tid = threadIdx.x;
    const int n0  = blockIdx.x * 8;

    if (tid < 8 * DDIM) {
        int j = tid / DDIM, d = tid % DDIM;
        e_sh[j][d] = E[(n0 + j) * DDIM + d];
    }
    __syncthreads();

    const int pbase = blockIdx.y * 1024 + tid * 4;
    #pragma unroll
    for (int q = 0; q < 4; ++q) {
        const int p  = pbase + q;
        const int o  = p >> 7;
        const int ki = p & 127;
        float wv[DDIM];
        #pragma unroll
        for (int d = 0; d < DDIM; ++d) wv[d] = wp[d * 8192 + ki * 64 + o];
        #pragma unroll
        for (int j = 0; j < 8; ++j) {
            float s = 0.0f;
            #pragma unroll
            for (int d = 0; d < DDIM; ++d) s += e_sh[j][d] * wv[d];
            __nv_bfloat16 hi, lo;
            bf16_split(s, hi, lo);
            size_t off = (size_t)(n0 + j) * 8192 + p;
            g_Wh[off] = hi;
            g_Wl[off] = lo;
        }
    }
}

// ---------------------------------------------------------------------------
// Kernel 4: HMMA GEMM  y = support @ x  (3-term bf16 split, fp32 accum)
// 128x128x32 CTA tiles, 4 warps of 64x64, 128 threads, 2 stages, 2 CTAs/SM.
// ---------------------------------------------------------------------------
__device__ __forceinline__ void load_stage(uint32_t sbase, int tid,
                                           int rowBase, int colBase, int k0)
{
    const __nv_bfloat16* gA[2] = { g_Ahi, g_Alo };
    const __nv_bfloat16* gB[2] = { g_Bhi, g_Blo };
    #pragma unroll
    for (int t = 0; t < 2; ++t) {
        #pragma unroll
        for (int i = 0; i < 4; ++i) {
            int seg = tid + i * 128;          // 0..511
            int r = seg >> 2, s = seg & 3;
            const void* g = gA[t] + (size_t)(rowBase + r) * KPAD + k0 + s * 8;
            CPASYNC16(sbase + t * TILE_B + r * APITCH + s * 16, g);
        }
    }
    #pragma unroll
    for (int t = 0; t < 2; ++t) {
        #pragma unroll
        for (int i = 0; i < 4; ++i) {
            int seg = tid + i * 128;
            int r = seg >> 2, s = seg & 3;
            const void* g = gB[t] + (size_t)(colBase + r) * KPAD + k0 + s * 8;
            CPASYNC16(sbase + (2 + t) * TILE_B + r * APITCH + s * 16, g);
        }
    }
}

__global__ void __launch_bounds__(128, 2)
gemm_kernel()
{
    extern __shared__ char dsmem[];
    const uint32_t sb = smem_u32(dsmem);
    const int tid  = threadIdx.x;
    const int warp = tid >> 5;
    const int lane = tid & 31;
    const int wm   = (warp & 1) * 64;   // warp m offset (2 x 64)
    const int wn   = (warp >> 1) * 64;  // warp n offset (2 x 64)

    // Grid swizzle: groups of 8 column-tiles keep B panels L2-resident.
    const int bid = blockIdx.y * gridDim.x + blockIdx.x;
    const int per = 8 * (MPAD / BM);            // 320
    const int grp = bid / per;
    const int rem = bid % per;
    const int rowBase = (rem / 8) * BM;
    const int colBase = (grp * 8 + (rem & 7)) * BN;

    float acc[4][8][4];
    #pragma unroll
    for (int i = 0; i < 4; ++i)
        #pragma unroll
        for (int j = 0; j < 8; ++j)
            #pragma unroll
            for (int q = 0; q < 4; ++q) acc[i][j][q] = 0.0f;

    // Prologue: fill stage 0
    load_stage(sb, tid, rowBase, colBase, 0);
    asm volatile("cp.async.commit_group;");

    const uint32_t aRowOff = (uint32_t)((wm + (lane & 15)) * APITCH + ((lane >> 4) << 4));
    const uint32_t bRowOff = (uint32_t)((wn + ((lane >> 4) << 3) + (lane & 7)) * APITCH
                                        + (((lane >> 3) & 1) << 4));

    for (int ck = 0; ck < NKCH; ++ck) {
        if (ck + 1 < NKCH) {
            load_stage(sb + ((ck + 1) & 1) * STAGE_B, tid, rowBase, colBase,
                       (ck + 1) * BKC);
            asm volatile("cp.async.commit_group;");
            asm volatile("cp.async.wait_group 1;");
        } else {
            asm volatile("cp.async.wait_group 0;");
        }
        __syncthreads();

        const uint32_t st = sb + (ck & 1) * STAGE_B;
        const uint32_t sAh = st + 0 * TILE_B + aRowOff;
        const uint32_t sAl = st + 1 * TILE_B + aRowOff;
        const uint32_t sBh = st + 2 * TILE_B + bRowOff;
        const uint32_t sBl = st + 3 * TILE_B + bRowOff;

        #pragma unroll
        for (int ks = 0; ks < 2; ++ks) {
            const uint32_t kb = ks * 32;
            uint32_t ah[4][4], al[4][4];
            #pragma unroll
            for (int mt = 0; mt < 4; ++mt) {
                LDSM4(ah[mt][0], ah[mt][1], ah[mt][2], ah[mt][3],
                      sAh + mt * 16 * APITCH + kb);
                LDSM4(al[mt][0], al[mt][1], al[mt][2], al[mt][3],
                      sAl + mt * 16 * APITCH + kb);
            }
            #pragma unroll
            for (int np = 0; np < 4; ++np) {
                uint32_t bh[4], bl[4];
                LDSM4(bh[0], bh[1], bh[2], bh[3], sBh + np * 16 * APITCH + kb);
                LDSM4(bl[0], bl[1], bl[2], bl[3], sBl + np * 16 * APITCH + kb);
                #pragma unroll
                for (int mt = 0; mt < 4; ++mt) {
                    #pragma unroll
                    for (int j = 0; j < 2; ++j) {
                        const int nt = np * 2 + j;
                        MMA16816(acc[mt][nt], ah[mt], bh[j * 2], bh[j * 2 + 1]);
                        MMA16816(acc[mt][nt], al[mt], bh[j * 2], bh[j * 2 + 1]);
                        MMA16816(acc[mt][nt], ah[mt], bl[j * 2], bl[j * 2 + 1]);
                    }
                }
            }
        }
        __syncthreads();
    }

    // Epilogue: write y[col>>6][m][col&63]
    #pragma unroll
    for (int mt = 0; mt < 4; ++mt) {
        #pragma unroll
        for (int nt = 0; nt < 8; ++nt) {
            const int m   = rowBase + wm + mt * 16 + (lane >> 2);
            const int col = colBase + wn + nt * 8 + (lane & 3) * 2;
            const int b = col >> 6, c = col & 63;
            float* base = g_y + (size_t)b * PLANE + c;
            if (m < NNODE)
                *(float2*)(base + (size_t)m * CIN) =
                    make_float2(acc[mt][nt][0], acc[mt][nt][1]);
            if (m + 8 < NNODE)
                *(float2*)(base + (size_t)(m + 8) * CIN) =
                    make_float2(acc[mt][nt][2], acc[mt][nt][3]);
        }
    }
}

// ---------------------------------------------------------------------------
// Kernel 5: per-node HMMA.  out[b,n,o] = A_n(64x128) @ W_n(128x64) + bias_n.
// ---------------------------------------------------------------------------
#define NPITCH 272                       // 256B payload + 16B pad
#define NSM_AH 0
#define NSM_AL (64 * NPITCH)             // 17408
#define NSM_WH (2 * 64 * NPITCH)         // 34816
#define NSM_WL (3 * 64 * NPITCH)         // 52224
#define NSM_TOT (4 * 64 * NPITCH)        // 69632

__global__ void __launch_bounds__(256, 2)
node_mma_kernel(const float* __restrict__ X,
                const float* __restrict__ E,
                const float* __restrict__ bp,
                float* __restrict__ out)
{
    extern __shared__ char dsmem[];
    const uint32_t sb = smem_u32(dsmem);
    __shared__ float e_sh[DDIM];
    __shared__ float bias_sh[64];

    const int n    = blockIdx.x;
    const int tid  = threadIdx.x;
    const int warp = tid >> 5;
    const int lane = tid & 31;

    if (tid < DDIM) e_sh[tid] = E[n * DDIM + tid];

    // Stage W hi/lo
    {
        const uint4* wh = (const uint4*)(g_Wh + (size_t)n * 8192);
        const uint4* wl = (const uint4*)(g_Wl + (size_t)n * 8192);
        #pragma unroll
        for (int i = 0; i < 4; ++i) {
            int seg = tid + i * 256;         // 0..1023
            int o = seg >> 4, s = seg & 15;
            *(uint4*)(dsmem + NSM_WH + o * NPITCH + s * 16) = wh[seg];
            *(uint4*)(dsmem + NSM_WL + o * NPITCH + s * 16) = wl[seg];
        }
    }

    // Stage A hi/lo: rows b (64), 128 ki = [x row | y row], split to bf16.
    #pragma unroll
    for (int idx = tid; idx < 2048; idx += 256) {
        int b  = idx >> 5;
        int i4 = (idx & 31) * 4;
        float4 vv;
        if (i4 < 64)
            vv = *(const float4*)(X + (size_t)b * PLANE + (size_t)n * CIN + i4);
        else
            vv = *(const float4*)(g_y + (size_t)b * PLANE + (size_t)n * CIN + (i4 - 64));
        __nv_bfloat16 h[4], l[4];
        bf16_split(vv.x, h[0], l[0]);
        bf16_split(vv.y, h[1], l[1]);
        bf16_split(vv.z, h[2], l[2]);
        bf16_split(vv.w, h[3], l[3]);
        *(uint2*)(dsmem + NSM_AH + b * NPITCH + i4 * 2) = *(const uint2*)h;
        *(uint2*)(dsmem + NSM_AL + b * NPITCH + i4 * 2) = *(const uint2*)l;
    }

    __syncthreads();
    if (tid < 64) {
        float s = 0.0f;
        #pragma unroll
        for (int d = 0; d < DDIM; ++d) s += e_sh[d] * bp[d * COUT + tid];
        bias_sh[tid] = s;
    }

    const int wm = (warp & 3) * 16;
    const int wn = (warp >> 2) * 32;

    const uint32_t aOff = sb + NSM_AH
        + (uint32_t)((wm + (lane & 15)) * NPITCH + ((lane >> 4) << 4));
    const uint32_t bOff = sb + NSM_WH
        + (uint32_t)((wn + ((lane >> 4) << 3) + (lane & 7)) * NPITCH
                     + (((lane >> 3) & 1) << 4));

    float acc[4][4];
    #pragma unroll
    for (int j = 0; j < 4; ++j)
        #pragma unroll
        for (int q = 0; q < 4; ++q) acc[j][q] = 0.0f;

    #pragma unroll
    for (int ks = 0; ks < 8; ++ks) {
        const uint32_t kb = ks * 32;
        uint32_t ah[4], al[4];
        LDSM4(ah[0], ah[1], ah[2], ah[3], aOff + kb);
        LDSM4(al[0], al[1], al[2], al[3], aOff + (NSM_AL - NSM_AH) + kb);
        #pragma unroll
        for (int np = 0; np < 2; ++np) {
            uint32_t bh[4], bl[4];
            LDSM4(bh[0], bh[1], bh[2], bh[3], bOff + np * 16 * NPITCH + kb);
            LDSM4(bl[0], bl[1], bl[2], bl[3],
                  bOff + (NSM_WL - NSM_WH) + np * 16 * NPITCH + kb);
            #pragma unroll
            for (int j = 0; j < 2; ++j) {
                const int nt = np * 2 + j;
                MMA16816(acc[nt], ah, bh[j * 2], bh[j * 2 + 1]);
                MMA16816(acc[nt], al, bh[j * 2], bh[j * 2 + 1]);
                MMA16816(acc[nt], ah, bl[j * 2], bl[j * 2 + 1]);
            }
        }
    }

    __syncthreads();

    #pragma unroll
    for (int nt = 0; nt < 4; ++nt) {
        const int m   = wm + (lane >> 2);
        const int col = wn + nt * 8 + (lane & 3) * 2;
        const float b0 = bias_sh[col], b1 = bias_sh[col + 1];
        float* base = out + (size_t)n * COUT + col;
        *(float2*)(base + (size_t)m * PLANE) =
            make_float2(acc[nt][0] + b0, acc[nt][1] + b1);
        *(float2*)(base + (size_t)(m + 8) * PLANE) =
            make_float2(acc[nt][2] + b0, acc[nt][3] + b1);
    }
}

// ---------------------------------------------------------------------------
extern "C" void kernel_launch(void* const* d_in, const int* in_sizes, int n_in,
                              void* d_out, int out_size)
{
    const float* x  = (const float*)d_in[0];   // (64, 5000, 64)
    const float* E  = (const float*)d_in[1];   // (5000, 10)
    const float* wp = (const float*)d_in[2];   // (10, 2, 64, 64)
    const float* bp = (const float*)d_in[3];   // (10, 64)
    float* out = (float*)d_out;                // (64, 5000, 64)

    // 1) softmax(relu(E E^T)) rows -> bf16 hi/lo (padded)
    support_split_kernel<<<MPAD, 256>>>(E);

    // 2) transpose x -> B^T hi/lo (K-major, padded)
    dim3 gB(NCOLS / 32, KPAD / 32);
    convert_b_kernel<<<gB, dim3(32, 8)>>>(x);

    // 3) per-node weights W_T (bf16 hi/lo)
    dim3 gW(NNODE / 8, 8);
    wbuild_kernel<<<gW, 256>>>(E, wp);

    // 4) tensor-core GEMM (HMMA): y = support @ x
    cudaFuncSetAttribute(gemm_kernel,
                         cudaFuncAttributeMaxDynamicSharedMemorySize, GEMM_SMEM);
    dim3 gG(NCOLS / BN, MPAD / BM);
    gemm_kernel<<<gG, 128, GEMM_SMEM>>>();

    // 5) per-node HMMA contraction + bias
    cudaFuncSetAttribute(node_mma_kernel,
                         cudaFuncAttributeMaxDynamicSharedMemorySize, NSM_TOT);
    node_mma_kernel<<<NNODE, 256, NSM_TOT>>>(x, E, bp, out);
}